// round 2
// baseline (speedup 1.0000x reference)
#include <cuda_runtime.h>
#include <cstdint>
#include <cstddef>
#include <math.h>

#define B_ 128
#define S_ 512
#define F_ 128
#define L_ 1024

#define BM 128
#define BN 64
#define BK 16

// ---- scratch (device globals; no allocation allowed) ----
__device__ float g_h[B_ * L_];                       // current hidden state [B,L]
__device__ float g_G[B_ * 9216];                     // gate pre-activations
__device__ float g_Wd[4096 * L_];                    // folded+merged decoder weights [4096, L]
__device__ float g_bd[4096];                         // folded+merged decoder bias
__device__ float g_Hdec[(size_t)S_ * B_ * L_];       // all decoder hidden states [S,B,L]
__device__ float g_GI[(size_t)S_ * B_ * 3072];       // precomputed encoder input gates [S,B,3L]

// ---- software grid barrier (single-wave grids only) ----
__device__ unsigned g_cnt = 0;
__device__ unsigned g_gen = 0;

__device__ __forceinline__ void gsync(unsigned nCTA) {
    __syncthreads();
    if (threadIdx.x == 0) {
        volatile unsigned* gen = &g_gen;
        unsigned e = *gen;
        __threadfence();
        if (atomicAdd(&g_cnt, 1u) == nCTA - 1u) {
            atomicExch(&g_cnt, 0u);
            __threadfence();
            *gen = e + 1u;
        } else {
            while (*gen == e) {}
        }
        __threadfence();
    }
    __syncthreads();
}

__device__ __forceinline__ float sigf(float v) { return 1.f / (1.f + expf(-v)); }

// ============================================================
// Shared GEMM tile routine: computes 128x64 output block,
//   out[m, n] = sum_k A[m, k] * W[n, k]  (+bias)
// A: Abase (row stride lda), K range [0, kLen) local
// W: Wbase (row stride ldw), already offset to (col-block row 0, kStart)
// out: outBase (row stride ldG), already offset to column 0 of block
// ============================================================
__device__ __forceinline__ void do_gemm(
    const float* __restrict__ Abase, int lda,
    const float* __restrict__ Wbase, int ldw, int kLen,
    float* __restrict__ outBase, int ldG,
    float b0, float b1, float b2, float b3,
    float (*As)[BM + 4], float (*Ws)[BN + 4])
{
    const int tid = threadIdx.x;
    const int tx = tid & 15, ty = tid >> 4;

    float acc[8][4];
#pragma unroll
    for (int m = 0; m < 8; m++)
#pragma unroll
        for (int n = 0; n < 4; n++) acc[m][n] = 0.f;

    for (int kt = 0; kt < kLen; kt += BK) {
#pragma unroll
        for (int q = 0; q < 2; q++) {
            int g = tid + q * 256;
            int row = g >> 2, c4 = (g & 3) << 2;
            float4 v = *reinterpret_cast<const float4*>(
                &Abase[(size_t)row * lda + kt + c4]);
            As[c4 + 0][row] = v.x; As[c4 + 1][row] = v.y;
            As[c4 + 2][row] = v.z; As[c4 + 3][row] = v.w;
        }
        {
            int row = tid >> 2, c4 = (tid & 3) << 2;
            float4 v = *reinterpret_cast<const float4*>(
                &Wbase[(size_t)row * ldw + kt + c4]);
            Ws[c4 + 0][row] = v.x; Ws[c4 + 1][row] = v.y;
            Ws[c4 + 2][row] = v.z; Ws[c4 + 3][row] = v.w;
        }
        __syncthreads();
#pragma unroll
        for (int kk = 0; kk < BK; kk++) {
            float a[8], w[4];
            *reinterpret_cast<float4*>(&a[0]) = *reinterpret_cast<const float4*>(&As[kk][ty * 8]);
            *reinterpret_cast<float4*>(&a[4]) = *reinterpret_cast<const float4*>(&As[kk][ty * 8 + 4]);
            *reinterpret_cast<float4*>(&w[0]) = *reinterpret_cast<const float4*>(&Ws[kk][tx * 4]);
#pragma unroll
            for (int m = 0; m < 8; m++)
#pragma unroll
                for (int n = 0; n < 4; n++) acc[m][n] += a[m] * w[n];
        }
        __syncthreads();
    }

#pragma unroll
    for (int m = 0; m < 8; m++) {
        float4 o;
        o.x = acc[m][0] + b0; o.y = acc[m][1] + b1;
        o.z = acc[m][2] + b2; o.w = acc[m][3] + b3;
        *reinterpret_cast<float4*>(&outBase[(size_t)(ty * 8 + m) * ldG + tx * 4]) = o;
    }
}

// ============================================================
// Precompute ALL encoder input gates: g_GI[t,b,:] = x[b,t,:] @ W_ih_e^T + b_ih_e
// grid (S, 48)
// ============================================================
__global__ __launch_bounds__(256) void gi_gemm(const float* __restrict__ x,
                                               const float* __restrict__ Wih,
                                               const float* __restrict__ bih) {
    __shared__ __align__(16) float As[BK][BM + 4];
    __shared__ __align__(16) float Ws[BK][BN + 4];
    const int t = blockIdx.x, bx = blockIdx.y;
    const int tx = threadIdx.x & 15;
    float b0 = bih[bx * 64 + tx * 4 + 0], b1 = bih[bx * 64 + tx * 4 + 1];
    float b2 = bih[bx * 64 + tx * 4 + 2], b3 = bih[bx * 64 + tx * 4 + 3];
    do_gemm(x + (size_t)t * F_, S_ * F_,
            Wih + (size_t)(bx * 64) * F_, F_, F_,
            g_GI + (size_t)t * B_ * 3072 + bx * 64, 3072,
            b0, b1, b2, b3, As, Ws);
}

// ============================================================
// Persistent encoder: 144 CTAs, 512 steps internally.
// Per step: gh = h @ W_hh^T (K split 336/336/352 x 48 col-blocks), sync,
//           gate update h (uses precomputed g_GI), sync.
// ============================================================
__global__ __launch_bounds__(256) void enc_persist(const float* __restrict__ Whh,
                                                   const float* __restrict__ bhh) {
    __shared__ __align__(16) float As[BK][BM + 4];
    __shared__ __align__(16) float Ws[BK][BN + 4];

    const int cta = blockIdx.x;
    const int ks = cta / 48;
    const int bx = cta - ks * 48;
    const int kStart = (ks == 0) ? 0 : (ks == 1) ? 336 : 672;
    const int kLen = (ks == 2) ? 352 : 336;
    const int colStart = ks * 3072;
    const float* Wb = Whh + (size_t)(bx * 64) * L_ + kStart;
    float* outB = g_G + colStart + bx * 64;

    const int tx = threadIdx.x & 15;
    float b0 = 0.f, b1 = 0.f, b2 = 0.f, b3 = 0.f;
    if (ks == 0) {
        b0 = bhh[bx * 64 + tx * 4 + 0]; b1 = bhh[bx * 64 + tx * 4 + 1];
        b2 = bhh[bx * 64 + tx * 4 + 2]; b3 = bhh[bx * 64 + tx * 4 + 3];
    }

    const unsigned nCTA = gridDim.x;
    const int gid = blockIdx.x * 256 + threadIdx.x;
    const int gstride = nCTA * 256;

    // zero h
    for (int i = gid; i < B_ * L_; i += gstride) g_h[i] = 0.f;
    gsync(nCTA);

    for (int t = 0; t < S_; t++) {
        do_gemm(g_h + kStart, L_, Wb, L_, kLen, outB, 9216, b0, b1, b2, b3, As, Ws);
        gsync(nCTA);
        const float* GI = g_GI + (size_t)t * B_ * 3072;
        for (int idx = gid; idx < B_ * L_; idx += gstride) {
            int b = idx >> 10, l = idx & 1023;
            const float* gi = GI + (size_t)b * 3072;
            const float* gh = g_G + (size_t)b * 9216;
            float hr = gh[l]        + gh[3072 + l] + gh[6144 + l];
            float hz = gh[1024 + l] + gh[4096 + l] + gh[7168 + l];
            float hn = gh[2048 + l] + gh[5120 + l] + gh[8192 + l];
            float r = sigf(gi[l] + hr);
            float z = sigf(gi[1024 + l] + hz);
            float n = tanhf(gi[2048 + l] + r * hn);
            g_h[idx] = (1.f - z) * n + z * g_h[idx];
        }
        gsync(nCTA);
    }
}

// ============================================================
// Persistent decoder: 128 CTAs, 512 steps internally.
// Folded weights: G = h @ Wd^T (K split 512/512 x 64 col-blocks).
// ============================================================
__global__ __launch_bounds__(256) void dec_persist() {
    __shared__ __align__(16) float As[BK][BM + 4];
    __shared__ __align__(16) float Ws[BK][BN + 4];

    const int cta = blockIdx.x;
    const int ks = cta >> 6;
    const int bx = cta & 63;
    const int kStart = ks * 512;
    const int colStart = ks * 4096;
    const float* Wb = g_Wd + (size_t)(bx * 64) * L_ + kStart;
    float* outB = g_G + colStart + bx * 64;

    const int tx = threadIdx.x & 15;
    float b0 = 0.f, b1 = 0.f, b2 = 0.f, b3 = 0.f;
    if (ks == 0) {
        b0 = g_bd[bx * 64 + tx * 4 + 0]; b1 = g_bd[bx * 64 + tx * 4 + 1];
        b2 = g_bd[bx * 64 + tx * 4 + 2]; b3 = g_bd[bx * 64 + tx * 4 + 3];
    }

    const unsigned nCTA = gridDim.x;
    const int gid = blockIdx.x * 256 + threadIdx.x;
    const int gstride = nCTA * 256;

    for (int s = 0; s < S_; s++) {
        do_gemm(g_h + kStart, L_, Wb, L_, 512, outB, 8192, b0, b1, b2, b3, As, Ws);
        gsync(nCTA);
        float* hst = g_Hdec + (size_t)s * B_ * L_;
        for (int idx = gid; idx < B_ * L_; idx += gstride) {
            int b = idx >> 10, l = idx & 1023;
            const float* gh = g_G + (size_t)b * 8192;
            float pr = gh[l]        + gh[4096 + l];
            float pz = gh[1024 + l] + gh[5120 + l];
            float pi = gh[2048 + l] + gh[6144 + l];
            float ph = gh[3072 + l] + gh[7168 + l];
            float r = sigf(pr), z = sigf(pz);
            float n = tanhf(pi + r * ph);
            float hv = (1.f - z) * n + z * g_h[idx];
            g_h[idx] = hv;
            hst[idx] = hv;
        }
        gsync(nCTA);
    }
}

// ============================================================
// One-time prep: fold decoder input path through W_out and merge r/z.
//   rows [0,2L):  Wd = W_ih_d @ W_out + W_hh_d   (r,z merged)
//   rows [2L,3L): Wd = W_ih_d @ W_out             (inn)
//   rows [3L,4L): Wd = W_hh_d rows [2L,3L)        (hn)
// ============================================================
__global__ void prep_wd(const float* __restrict__ Wihd, const float* __restrict__ Whhd,
                        const float* __restrict__ bihd, const float* __restrict__ bhhd,
                        const float* __restrict__ Wout, const float* __restrict__ bout) {
    int k = blockIdx.x * blockDim.x + threadIdx.x;   // 0..1023
    int j = blockIdx.y;                              // 0..4095
    float v;
    if (j < 3072) {
        const float* wr = Wihd + (size_t)j * F_;
        float acc = 0.f;
        for (int f = 0; f < F_; f++) acc += wr[f] * Wout[(size_t)f * L_ + k];
        v = acc;
        if (j < 2048) v += Whhd[(size_t)j * L_ + k];
        if (k == 0) {
            float bb = 0.f;
            for (int f = 0; f < F_; f++) bb += wr[f] * bout[f];
            bb += bihd[j];
            if (j < 2048) bb += bhhd[j];
            g_bd[j] = bb;
        }
    } else {
        v = Whhd[(size_t)(j - 1024) * L_ + k];
        if (k == 0) g_bd[j] = bhhd[j - 1024];
    }
    g_Wd[(size_t)j * L_ + k] = v;
}

// ============================================================
// Final output GEMM: out[b, S-1-s, :] = Hdec[s,b,:] @ W_out^T + b_out
// ============================================================
__global__ __launch_bounds__(256) void out_gemm(const float* __restrict__ Wout,
                                                const float* __restrict__ bout,
                                                float* __restrict__ out) {
    __shared__ __align__(16) float As[BK][BM + 4];
    __shared__ __align__(16) float Ws[BK][BN + 4];
    const int s = blockIdx.x;
    const int nb = blockIdx.y;
    const float* A = g_Hdec + (size_t)s * (B_ * L_);
    const float* Wbase = Wout + (size_t)(nb * 64) * L_;

    const int tid = threadIdx.x;
    const int tx = tid & 15, ty = tid >> 4;

    float acc[8][4];
#pragma unroll
    for (int m = 0; m < 8; m++)
#pragma unroll
        for (int n = 0; n < 4; n++) acc[m][n] = 0.f;

    for (int kt = 0; kt < L_; kt += BK) {
#pragma unroll
        for (int q = 0; q < 2; q++) {
            int g = tid + q * 256;
            int row = g >> 2, c4 = (g & 3) << 2;
            float4 v = *reinterpret_cast<const float4*>(&A[(size_t)row * L_ + kt + c4]);
            As[c4 + 0][row] = v.x; As[c4 + 1][row] = v.y;
            As[c4 + 2][row] = v.z; As[c4 + 3][row] = v.w;
        }
        {
            int row = tid >> 2, c4 = (tid & 3) << 2;
            float4 v = *reinterpret_cast<const float4*>(&Wbase[(size_t)row * L_ + kt + c4]);
            Ws[c4 + 0][row] = v.x; Ws[c4 + 1][row] = v.y;
            Ws[c4 + 2][row] = v.z; Ws[c4 + 3][row] = v.w;
        }
        __syncthreads();
#pragma unroll
        for (int kk = 0; kk < BK; kk++) {
            float a[8], w[4];
            *reinterpret_cast<float4*>(&a[0]) = *reinterpret_cast<const float4*>(&As[kk][ty * 8]);
            *reinterpret_cast<float4*>(&a[4]) = *reinterpret_cast<const float4*>(&As[kk][ty * 8 + 4]);
            *reinterpret_cast<float4*>(&w[0]) = *reinterpret_cast<const float4*>(&Ws[kk][tx * 4]);
#pragma unroll
            for (int m = 0; m < 8; m++)
#pragma unroll
                for (int n = 0; n < 4; n++) acc[m][n] += a[m] * w[n];
        }
        __syncthreads();
    }

    const int f0 = nb * 64 + tx * 4;
    float b0 = bout[f0], b1 = bout[f0 + 1], b2 = bout[f0 + 2], b3 = bout[f0 + 3];
#pragma unroll
    for (int m = 0; m < 8; m++) {
        int b = ty * 8 + m;
        float4 o;
        o.x = acc[m][0] + b0; o.y = acc[m][1] + b1;
        o.z = acc[m][2] + b2; o.w = acc[m][3] + b3;
        *reinterpret_cast<float4*>(&out[((size_t)b * S_ + (S_ - 1 - s)) * F_ + f0]) = o;
    }
}

// ============================================================
// Launch: 5 graph nodes total.
// ============================================================
extern "C" void kernel_launch(void* const* d_in, const int* in_sizes, int n_in,
                              void* d_out, int out_size) {
    const float* x      = (const float*)d_in[0];
    const float* W_ih_e = (const float*)d_in[1];
    const float* W_hh_e = (const float*)d_in[2];
    const float* b_ih_e = (const float*)d_in[3];
    const float* b_hh_e = (const float*)d_in[4];
    const float* W_ih_d = (const float*)d_in[5];
    const float* W_hh_d = (const float*)d_in[6];
    const float* b_ih_d = (const float*)d_in[7];
    const float* b_hh_d = (const float*)d_in[8];
    const float* W_out  = (const float*)d_in[9];
    const float* b_out  = (const float*)d_in[10];
    float* out = (float*)d_out;

    prep_wd<<<dim3(4, 4096), 256>>>(W_ih_d, W_hh_d, b_ih_d, b_hh_d, W_out, b_out);
    gi_gemm<<<dim3(S_, 48), 256>>>(x, W_ih_e, b_ih_e);
    enc_persist<<<144, 256>>>(W_hh_e, b_hh_e);
    dec_persist<<<128, 256>>>();
    out_gemm<<<dim3(S_, 2), 256>>>(W_out, b_out, out);
}

// round 3
// speedup vs baseline: 1.0102x; 1.0102x over previous
#include <cuda_runtime.h>
#include <cstdint>
#include <cstddef>
#include <math.h>

#define B_ 128
#define S_ 512
#define F_ 128
#define L_ 1024

#define BM 128
#define BN 64
#define BK 16

// ---- scratch (device globals; no allocation allowed) ----
__device__ float g_h[B_ * L_];                       // current hidden state [B,L]
__device__ float g_G[B_ * 9216];                     // gate pre-activations
__device__ float g_Wd[4096 * L_];                    // folded+merged decoder weights [4096, L]
__device__ float g_bd[4096];                         // folded+merged decoder bias
__device__ float g_Hdec[(size_t)S_ * B_ * L_];       // all decoder hidden states [S,B,L]
__device__ float g_GI[(size_t)S_ * B_ * 3072];       // precomputed encoder input gates [S,B,3L]

// ---- software grid barrier (single-wave grids only) ----
__device__ unsigned g_cnt = 0;
__device__ unsigned g_gen = 0;

__device__ __forceinline__ void gsync(unsigned nCTA) {
    __syncthreads();
    if (threadIdx.x == 0) {
        volatile unsigned* gen = &g_gen;
        unsigned e = *gen;
        __threadfence();
        if (atomicAdd(&g_cnt, 1u) == nCTA - 1u) {
            atomicExch(&g_cnt, 0u);
            __threadfence();
            *gen = e + 1u;
        } else {
            while (*gen == e) {}
        }
        __threadfence();
    }
    __syncthreads();
}

__device__ __forceinline__ float sigf(float v) { return 1.f / (1.f + expf(-v)); }

// ============================================================
// Shared GEMM tile routine: computes 128x64 output block,
//   out[m, n] = sum_k A[m, k] * W[n, k]  (+bias)
// A: Abase (row stride lda), K range [0, kLen) local
// W: Wbase (row stride ldw), already offset to (col-block row 0, kStart)
// out: outBase (row stride ldG), already offset to column 0 of block
// ============================================================
__device__ __forceinline__ void do_gemm(
    const float* __restrict__ Abase, int lda,
    const float* __restrict__ Wbase, int ldw, int kLen,
    float* __restrict__ outBase, int ldG,
    float b0, float b1, float b2, float b3,
    float (*As)[BM + 4], float (*Ws)[BN + 4])
{
    const int tid = threadIdx.x;
    const int tx = tid & 15, ty = tid >> 4;

    float acc[8][4];
#pragma unroll
    for (int m = 0; m < 8; m++)
#pragma unroll
        for (int n = 0; n < 4; n++) acc[m][n] = 0.f;

    for (int kt = 0; kt < kLen; kt += BK) {
#pragma unroll
        for (int q = 0; q < 2; q++) {
            int g = tid + q * 256;
            int row = g >> 2, c4 = (g & 3) << 2;
            float4 v = *reinterpret_cast<const float4*>(
                &Abase[(size_t)row * lda + kt + c4]);
            As[c4 + 0][row] = v.x; As[c4 + 1][row] = v.y;
            As[c4 + 2][row] = v.z; As[c4 + 3][row] = v.w;
        }
        {
            int row = tid >> 2, c4 = (tid & 3) << 2;
            float4 v = *reinterpret_cast<const float4*>(
                &Wbase[(size_t)row * ldw + kt + c4]);
            Ws[c4 + 0][row] = v.x; Ws[c4 + 1][row] = v.y;
            Ws[c4 + 2][row] = v.z; Ws[c4 + 3][row] = v.w;
        }
        __syncthreads();
#pragma unroll
        for (int kk = 0; kk < BK; kk++) {
            float a[8], w[4];
            *reinterpret_cast<float4*>(&a[0]) = *reinterpret_cast<const float4*>(&As[kk][ty * 8]);
            *reinterpret_cast<float4*>(&a[4]) = *reinterpret_cast<const float4*>(&As[kk][ty * 8 + 4]);
            *reinterpret_cast<float4*>(&w[0]) = *reinterpret_cast<const float4*>(&Ws[kk][tx * 4]);
#pragma unroll
            for (int m = 0; m < 8; m++)
#pragma unroll
                for (int n = 0; n < 4; n++) acc[m][n] += a[m] * w[n];
        }
        __syncthreads();
    }

#pragma unroll
    for (int m = 0; m < 8; m++) {
        float4 o;
        o.x = acc[m][0] + b0; o.y = acc[m][1] + b1;
        o.z = acc[m][2] + b2; o.w = acc[m][3] + b3;
        *reinterpret_cast<float4*>(&outBase[(size_t)(ty * 8 + m) * ldG + tx * 4]) = o;
    }
}

// ============================================================
// Precompute ALL encoder input gates: g_GI[t,b,:] = x[b,t,:] @ W_ih_e^T + b_ih_e
// grid (S, 48)
// ============================================================
__global__ __launch_bounds__(256) void gi_gemm(const float* __restrict__ x,
                                               const float* __restrict__ Wih,
                                               const float* __restrict__ bih) {
    __shared__ __align__(16) float As[BK][BM + 4];
    __shared__ __align__(16) float Ws[BK][BN + 4];
    const int t = blockIdx.x, bx = blockIdx.y;
    const int tx = threadIdx.x & 15;
    float b0 = bih[bx * 64 + tx * 4 + 0], b1 = bih[bx * 64 + tx * 4 + 1];
    float b2 = bih[bx * 64 + tx * 4 + 2], b3 = bih[bx * 64 + tx * 4 + 3];
    do_gemm(x + (size_t)t * F_, S_ * F_,
            Wih + (size_t)(bx * 64) * F_, F_, F_,
            g_GI + (size_t)t * B_ * 3072 + bx * 64, 3072,
            b0, b1, b2, b3, As, Ws);
}

// ============================================================
// Persistent encoder: 144 CTAs, 512 steps internally.
// Per step: gh = h @ W_hh^T (K split 336/336/352 x 48 col-blocks), sync,
//           gate update h (uses precomputed g_GI), sync.
// ============================================================
__global__ __launch_bounds__(256) void enc_persist(const float* __restrict__ Whh,
                                                   const float* __restrict__ bhh) {
    __shared__ __align__(16) float As[BK][BM + 4];
    __shared__ __align__(16) float Ws[BK][BN + 4];

    const int cta = blockIdx.x;
    const int ks = cta / 48;
    const int bx = cta - ks * 48;
    const int kStart = (ks == 0) ? 0 : (ks == 1) ? 336 : 672;
    const int kLen = (ks == 2) ? 352 : 336;
    const int colStart = ks * 3072;
    const float* Wb = Whh + (size_t)(bx * 64) * L_ + kStart;
    float* outB = g_G + colStart + bx * 64;

    const int tx = threadIdx.x & 15;
    float b0 = 0.f, b1 = 0.f, b2 = 0.f, b3 = 0.f;
    if (ks == 0) {
        b0 = bhh[bx * 64 + tx * 4 + 0]; b1 = bhh[bx * 64 + tx * 4 + 1];
        b2 = bhh[bx * 64 + tx * 4 + 2]; b3 = bhh[bx * 64 + tx * 4 + 3];
    }

    const unsigned nCTA = gridDim.x;
    const int gid = blockIdx.x * 256 + threadIdx.x;
    const int gstride = nCTA * 256;

    // zero h
    for (int i = gid; i < B_ * L_; i += gstride) g_h[i] = 0.f;
    gsync(nCTA);

    for (int t = 0; t < S_; t++) {
        do_gemm(g_h + kStart, L_, Wb, L_, kLen, outB, 9216, b0, b1, b2, b3, As, Ws);
        gsync(nCTA);
        const float* GI = g_GI + (size_t)t * B_ * 3072;
        for (int idx = gid; idx < B_ * L_; idx += gstride) {
            int b = idx >> 10, l = idx & 1023;
            const float* gi = GI + (size_t)b * 3072;
            const float* gh = g_G + (size_t)b * 9216;
            float hr = gh[l]        + gh[3072 + l] + gh[6144 + l];
            float hz = gh[1024 + l] + gh[4096 + l] + gh[7168 + l];
            float hn = gh[2048 + l] + gh[5120 + l] + gh[8192 + l];
            float r = sigf(gi[l] + hr);
            float z = sigf(gi[1024 + l] + hz);
            float n = tanhf(gi[2048 + l] + r * hn);
            g_h[idx] = (1.f - z) * n + z * g_h[idx];
        }
        gsync(nCTA);
    }
}

// ============================================================
// Persistent decoder: 128 CTAs, 512 steps internally.
// Folded weights: G = h @ Wd^T (K split 512/512 x 64 col-blocks).
// ============================================================
__global__ __launch_bounds__(256) void dec_persist() {
    __shared__ __align__(16) float As[BK][BM + 4];
    __shared__ __align__(16) float Ws[BK][BN + 4];

    const int cta = blockIdx.x;
    const int ks = cta >> 6;
    const int bx = cta & 63;
    const int kStart = ks * 512;
    const int colStart = ks * 4096;
    const float* Wb = g_Wd + (size_t)(bx * 64) * L_ + kStart;
    float* outB = g_G + colStart + bx * 64;

    const int tx = threadIdx.x & 15;
    float b0 = 0.f, b1 = 0.f, b2 = 0.f, b3 = 0.f;
    if (ks == 0) {
        b0 = g_bd[bx * 64 + tx * 4 + 0]; b1 = g_bd[bx * 64 + tx * 4 + 1];
        b2 = g_bd[bx * 64 + tx * 4 + 2]; b3 = g_bd[bx * 64 + tx * 4 + 3];
    }

    const unsigned nCTA = gridDim.x;
    const int gid = blockIdx.x * 256 + threadIdx.x;
    const int gstride = nCTA * 256;

    for (int s = 0; s < S_; s++) {
        do_gemm(g_h + kStart, L_, Wb, L_, 512, outB, 8192, b0, b1, b2, b3, As, Ws);
        gsync(nCTA);
        float* hst = g_Hdec + (size_t)s * B_ * L_;
        for (int idx = gid; idx < B_ * L_; idx += gstride) {
            int b = idx >> 10, l = idx & 1023;
            const float* gh = g_G + (size_t)b * 8192;
            float pr = gh[l]        + gh[4096 + l];
            float pz = gh[1024 + l] + gh[5120 + l];
            float pi = gh[2048 + l] + gh[6144 + l];
            float ph = gh[3072 + l] + gh[7168 + l];
            float r = sigf(pr), z = sigf(pz);
            float n = tanhf(pi + r * ph);
            float hv = (1.f - z) * n + z * g_h[idx];
            g_h[idx] = hv;
            hst[idx] = hv;
        }
        gsync(nCTA);
    }
}

// ============================================================
// One-time prep: fold decoder input path through W_out and merge r/z.
//   rows [0,2L):  Wd = W_ih_d @ W_out + W_hh_d   (r,z merged)
//   rows [2L,3L): Wd = W_ih_d @ W_out             (inn)
//   rows [3L,4L): Wd = W_hh_d rows [2L,3L)        (hn)
// ============================================================
__global__ void prep_wd(const float* __restrict__ Wihd, const float* __restrict__ Whhd,
                        const float* __restrict__ bihd, const float* __restrict__ bhhd,
                        const float* __restrict__ Wout, const float* __restrict__ bout) {
    int k = blockIdx.x * blockDim.x + threadIdx.x;   // 0..1023
    int j = blockIdx.y;                              // 0..4095
    float v;
    if (j < 3072) {
        const float* wr = Wihd + (size_t)j * F_;
        float acc = 0.f;
        for (int f = 0; f < F_; f++) acc += wr[f] * Wout[(size_t)f * L_ + k];
        v = acc;
        if (j < 2048) v += Whhd[(size_t)j * L_ + k];
        if (k == 0) {
            float bb = 0.f;
            for (int f = 0; f < F_; f++) bb += wr[f] * bout[f];
            bb += bihd[j];
            if (j < 2048) bb += bhhd[j];
            g_bd[j] = bb;
        }
    } else {
        v = Whhd[(size_t)(j - 1024) * L_ + k];
        if (k == 0) g_bd[j] = bhhd[j - 1024];
    }
    g_Wd[(size_t)j * L_ + k] = v;
}

// ============================================================
// Final output GEMM: out[b, S-1-s, :] = Hdec[s,b,:] @ W_out^T + b_out
// ============================================================
__global__ __launch_bounds__(256) void out_gemm(const float* __restrict__ Wout,
                                                const float* __restrict__ bout,
                                                float* __restrict__ out) {
    __shared__ __align__(16) float As[BK][BM + 4];
    __shared__ __align__(16) float Ws[BK][BN + 4];
    const int s = blockIdx.x;
    const int nb = blockIdx.y;
    const float* A = g_Hdec + (size_t)s * (B_ * L_);
    const float* Wbase = Wout + (size_t)(nb * 64) * L_;

    const int tid = threadIdx.x;
    const int tx = tid & 15, ty = tid >> 4;

    float acc[8][4];
#pragma unroll
    for (int m = 0; m < 8; m++)
#pragma unroll
        for (int n = 0; n < 4; n++) acc[m][n] = 0.f;

    for (int kt = 0; kt < L_; kt += BK) {
#pragma unroll
        for (int q = 0; q < 2; q++) {
            int g = tid + q * 256;
            int row = g >> 2, c4 = (g & 3) << 2;
            float4 v = *reinterpret_cast<const float4*>(&A[(size_t)row * L_ + kt + c4]);
            As[c4 + 0][row] = v.x; As[c4 + 1][row] = v.y;
            As[c4 + 2][row] = v.z; As[c4 + 3][row] = v.w;
        }
        {
            int row = tid >> 2, c4 = (tid & 3) << 2;
            float4 v = *reinterpret_cast<const float4*>(&Wbase[(size_t)row * L_ + kt + c4]);
            Ws[c4 + 0][row] = v.x; Ws[c4 + 1][row] = v.y;
            Ws[c4 + 2][row] = v.z; Ws[c4 + 3][row] = v.w;
        }
        __syncthreads();
#pragma unroll
        for (int kk = 0; kk < BK; kk++) {
            float a[8], w[4];
            *reinterpret_cast<float4*>(&a[0]) = *reinterpret_cast<const float4*>(&As[kk][ty * 8]);
            *reinterpret_cast<float4*>(&a[4]) = *reinterpret_cast<const float4*>(&As[kk][ty * 8 + 4]);
            *reinterpret_cast<float4*>(&w[0]) = *reinterpret_cast<const float4*>(&Ws[kk][tx * 4]);
#pragma unroll
            for (int m = 0; m < 8; m++)
#pragma unroll
                for (int n = 0; n < 4; n++) acc[m][n] += a[m] * w[n];
        }
        __syncthreads();
    }

    const int f0 = nb * 64 + tx * 4;
    float b0 = bout[f0], b1 = bout[f0 + 1], b2 = bout[f0 + 2], b3 = bout[f0 + 3];
#pragma unroll
    for (int m = 0; m < 8; m++) {
        int b = ty * 8 + m;
        float4 o;
        o.x = acc[m][0] + b0; o.y = acc[m][1] + b1;
        o.z = acc[m][2] + b2; o.w = acc[m][3] + b3;
        *reinterpret_cast<float4*>(&out[((size_t)b * S_ + (S_ - 1 - s)) * F_ + f0]) = o;
    }
}

// ============================================================
// Launch: 5 graph nodes total.
// ============================================================
extern "C" void kernel_launch(void* const* d_in, const int* in_sizes, int n_in,
                              void* d_out, int out_size) {
    const float* x      = (const float*)d_in[0];
    const float* W_ih_e = (const float*)d_in[1];
    const float* W_hh_e = (const float*)d_in[2];
    const float* b_ih_e = (const float*)d_in[3];
    const float* b_hh_e = (const float*)d_in[4];
    const float* W_ih_d = (const float*)d_in[5];
    const float* W_hh_d = (const float*)d_in[6];
    const float* b_ih_d = (const float*)d_in[7];
    const float* b_hh_d = (const float*)d_in[8];
    const float* W_out  = (const float*)d_in[9];
    const float* b_out  = (const float*)d_in[10];
    float* out = (float*)d_out;

    prep_wd<<<dim3(4, 4096), 256>>>(W_ih_d, W_hh_d, b_ih_d, b_hh_d, W_out, b_out);
    gi_gemm<<<dim3(S_, 48), 256>>>(x, W_ih_e, b_ih_e);
    enc_persist<<<144, 256>>>(W_hh_e, b_hh_e);
    dec_persist<<<128, 256>>>();
    out_gemm<<<dim3(S_, 2), 256>>>(W_out, b_out, out);
}